// round 1
// baseline (speedup 1.0000x reference)
#include <cuda_runtime.h>

#define KK 9
#define TPB 256
#define GRID 1216

// Block partial sums (fixed-size scratch; no allocation allowed).
__device__ float g_partials[GRID];

// Per-row loss given the 9 logits (in registers) and label yi.
// stw = smem tail-weight table [9][9]: (|k-y|-1)^3 for |k-y|>1 else 0.
__device__ __forceinline__ float row_loss(const float* l, int yi, const float* stw) {
    // softmax pieces
    float m = l[0];
#pragma unroll
    for (int k = 1; k < KK; k++) m = fmaxf(m, l[k]);

    float e[KK];
    float S = 0.f, xy = 0.f;
#pragma unroll
    for (int k = 0; k < KK; k++) {
        float t = l[k] - m;
        e[k] = __expf(t);
        S += e[k];
        xy = (k == yi) ? t : xy;   // l[y]-m, selected branchlessly
    }
    float logS = __logf(S);
    float invS = __fdividef(1.f, S);

    // clamp_min(eps) + renormalize (matches reference exactly)
    float Z = 0.f;
#pragma unroll
    for (int k = 0; k < KK; k++) {
        e[k] = fmaxf(e[k] * invS, 1e-8f);
        Z += e[k];
    }
    float invZ = __fdividef(1.f, Z);

    // cdf weights = widths/95, as immediates (fully unrolled)
    const float cw[KK] = {3.f/95.f, 7.f/95.f, 10.f/95.f, 10.f/95.f, 10.f/95.f,
                          10.f/95.f, 10.f/95.f, 10.f/95.f, 25.f/95.f};

    float c = 0.f, tail = 0.f, farmax = -1e30f, nmax = 0.f, py = 0.f, emd = 0.f;
#pragma unroll
    for (int k = 0; k < KK; k++) {
        float p = e[k] * invZ;
        float w = stw[yi * KK + k];          // conflict-free LDS (9 distinct banks)
        tail = fmaf(p, w, tail);
        int ad = k - yi; ad = ad < 0 ? -ad : ad;
        farmax = (ad > 1)  ? fmaxf(farmax, p) : farmax;
        nmax   = (ad == 1) ? fmaxf(nmax, p)   : nmax;
        py     = (ad == 0) ? p                : py;
        c += p;
        float diff = c - ((k <= yi) ? 1.f : 0.f);
        emd = fmaf(diff * diff, cw[k], emd);
    }

    float nll = logS - xy;                               // -log_softmax[y]
    float fm  = fmaxf(farmax - py + 0.15f, 0.f);         // FarProbMargin
    float lp  = fmaxf(nmax   - py + 0.35f, 0.f);         // LocalPeak
    // ce*INV_LOGK + ALPHA*(7*fm + 9*tail + 12*lp + 1.2*emd)
    return 0.45511961331341866f * nll
         + 2.8f * fm + 3.6f * tail + 4.8f * lp + 0.48f * emd;
}

__global__ void __launch_bounds__(TPB)
loss_kernel(const float* __restrict__ logits, const int* __restrict__ y, int B) {
    __shared__ float4 s4[(TPB * KK) / 4];   // 576 float4 = 9216 B tile
    __shared__ float  stw[KK * KK];
    __shared__ float  wsum[TPB / 32];
    float* sl = (float*)s4;

    // build tail-weight table once
    if (threadIdx.x < KK * KK) {
        int yy = threadIdx.x / KK, kk = threadIdx.x % KK;
        int d = kk - yy; d = d < 0 ? -d : d;
        float dm1 = (float)(d - 1);
        stw[threadIdx.x] = (d > 1) ? dm1 * dm1 * dm1 : 0.f;
    }
    __syncthreads();

    int numTiles = B / TPB;
    float acc = 0.f;

    for (int t = blockIdx.x; t < numTiles; t += gridDim.x) {
        // coalesced float4 stage of a 256-row tile into smem
        const float4* src = (const float4*)(logits + (size_t)t * (TPB * KK));
#pragma unroll 3
        for (int j = threadIdx.x; j < (TPB * KK) / 4; j += TPB)
            s4[j] = src[j];
        __syncthreads();

        int row = t * TPB + threadIdx.x;
        int yi = __ldg(&y[row]);
        float l[KK];
#pragma unroll
        for (int k = 0; k < KK; k++)
            l[k] = sl[threadIdx.x * KK + k];   // stride 9: bank-conflict-free

        acc += row_loss(l, yi, stw);
        __syncthreads();   // protect smem before next tile overwrite
    }

    // remainder rows (B not multiple of 256) — direct global path, block 0
    int rem_start = numTiles * TPB;
    if (blockIdx.x == 0 && rem_start + (int)threadIdx.x < B) {
        int row = rem_start + threadIdx.x;
        float l[KK];
#pragma unroll
        for (int k = 0; k < KK; k++)
            l[k] = logits[(size_t)row * KK + k];
        acc += row_loss(l, __ldg(&y[row]), stw);
    }

    // block reduction (deterministic: no float atomics)
#pragma unroll
    for (int o = 16; o > 0; o >>= 1)
        acc += __shfl_xor_sync(0xffffffffu, acc, o);
    if ((threadIdx.x & 31) == 0) wsum[threadIdx.x >> 5] = acc;
    __syncthreads();
    if (threadIdx.x == 0) {
        float s = 0.f;
#pragma unroll
        for (int i = 0; i < TPB / 32; i++) s += wsum[i];
        g_partials[blockIdx.x] = s;
    }
}

__global__ void __launch_bounds__(1024)
reduce_kernel(float* __restrict__ out, float invB) {
    __shared__ float ws[32];
    float s = 0.f;
    for (int i = threadIdx.x; i < GRID; i += 1024)
        s += g_partials[i];
#pragma unroll
    for (int o = 16; o > 0; o >>= 1)
        s += __shfl_xor_sync(0xffffffffu, s, o);
    if ((threadIdx.x & 31) == 0) ws[threadIdx.x >> 5] = s;
    __syncthreads();
    if (threadIdx.x == 0) {
        float t = 0.f;
#pragma unroll
        for (int i = 0; i < 32; i++) t += ws[i];
        out[0] = t * invB;
    }
}

extern "C" void kernel_launch(void* const* d_in, const int* in_sizes, int n_in,
                              void* d_out, int out_size) {
    const float* logits = (const float*)d_in[0];
    const int*   y      = (const int*)d_in[1];
    int B = in_sizes[1];   // label count = row count
    loss_kernel<<<GRID, TPB>>>(logits, y, B);
    reduce_kernel<<<1, 1024>>>((float*)d_out, 1.f / (float)B);
}

// round 2
// speedup vs baseline: 1.8134x; 1.8134x over previous
#include <cuda_runtime.h>

#define KK 9
#define TPB 256
#define GRID 888
#define TILE TPB
#define TILE_F4 ((TILE * KK) / 4)   /* 576 float4 = 9216 B per tile */

__device__ float g_part[GRID];
__device__ unsigned g_ticket = 0;

// Core per-row loss. l[9] in registers, ly = l[yi], stw = smem tail-weight table.
// All softmax normalization deferred: works on unnormalized e_k = exp(l_k).
__device__ __forceinline__ float row_core(const float* l, int yi, float ly, const float* stw) {
    float e[KK], C[KK];
    float c = 0.f;
#pragma unroll
    for (int k = 0; k < KK; k++) { e[k] = __expf(l[k]); c += e[k]; C[k] = c; }
    float S = c;
    float py_u = __expf(ly);

    const float* tw = stw + yi * KK;
    const float cw[KK] = {3.f/95.f, 7.f/95.f, 10.f/95.f, 10.f/95.f, 10.f/95.f,
                          10.f/95.f, 10.f/95.f, 10.f/95.f, 25.f/95.f};
    float tail_u = 0.f, far_u = 0.f, nbr_u = 0.f, emd_u = 0.f;
#pragma unroll
    for (int k = 0; k < KK; k++) {
        tail_u = fmaf(e[k], tw[k], tail_u);          // tail weight (smem, conflict-free)
        int dk = k - yi;
        unsigned v = (unsigned)(dk + 1);
        if (v > 2u)            far_u = fmaxf(far_u, e[k]);   // |k-y| > 1
        if ((v & ~2u) == 0u)   nbr_u = fmaxf(nbr_u, e[k]);   // |k-y| == 1
        if (k < KK - 1) {                             // k=8 term is exactly 0
            float d = (dk <= 0) ? (C[k] - S) : C[k]; // cdf_pred - cdf_true (unnormalized)
            emd_u = fmaf(d * d, cw[k], emd_u);
        }
    }
    float invS = __fdividef(1.f, S);
    float logS = __logf(S);
    float nll  = logS - ly;                           // -log_softmax[y], exact
    float py   = py_u * invS;
    float fm   = fmaxf(fmaf(far_u, invS, 0.15f - py), 0.f);  // FarProbMargin
    float lp   = fmaxf(fmaf(nbr_u, invS, 0.35f - py), 0.f);  // LocalPeak
    // ce*INV_LOGK + ALPHA*(7*fm + 9*tail + 12*lp + 1.2*emd)
    return 0.45511961331341866f * nll
         + 2.8f * fm + 3.6f * (tail_u * invS) + 4.8f * lp
         + 0.48f * (emd_u * invS * invS);
}

__global__ void __launch_bounds__(TPB)
loss_kernel(const float* __restrict__ logits, const int* __restrict__ y,
            float* __restrict__ out, int B, float invB) {
    __shared__ float4 s4[TILE_F4];
    __shared__ float  stw[KK * KK];
    __shared__ float  wsum[TPB / 32];
    __shared__ int    s_last;
    float* sl = (float*)s4;

    if (threadIdx.x < KK * KK) {
        int yy = threadIdx.x / KK, kk = threadIdx.x % KK;
        int d = kk - yy; int ad = d < 0 ? -d : d;
        int dm1 = ad - 1;
        stw[threadIdx.x] = (ad > 1) ? (float)(dm1 * dm1 * dm1) : 0.f;
    }
    __syncthreads();

    int numTiles = B / TILE;
    float acc = 0.f;

    // software-pipelined: prefetch tile t+GRID while computing tile t
    int t = blockIdx.x;
    float4 r0 = make_float4(0,0,0,0), r1 = r0, r2 = r0;
    bool valid = (t < numTiles);
    if (valid) {
        const float4* src = (const float4*)logits + (size_t)t * TILE_F4;
        r0 = src[threadIdx.x];
        r1 = src[threadIdx.x + TPB];
        if (threadIdx.x < TILE_F4 - 2 * TPB) r2 = src[threadIdx.x + 2 * TPB];
    }
    while (valid) {
        s4[threadIdx.x]       = r0;
        s4[threadIdx.x + TPB] = r1;
        if (threadIdx.x < TILE_F4 - 2 * TPB) s4[threadIdx.x + 2 * TPB] = r2;
        int yi = y[t * TILE + threadIdx.x];
        __syncthreads();

        float l[KK];
        const float* lrow = sl + threadIdx.x * KK;    // stride 9: conflict-free
#pragma unroll
        for (int k = 0; k < KK; k++) l[k] = lrow[k];
        float ly = sl[threadIdx.x * KK + yi];         // dynamic, near-conflict-free
        __syncthreads();

        int tn = t + GRID;
        valid = tn < numTiles;
        if (valid) {                                   // prefetch overlaps compute below
            const float4* src = (const float4*)logits + (size_t)tn * TILE_F4;
            r0 = src[threadIdx.x];
            r1 = src[threadIdx.x + TPB];
            if (threadIdx.x < TILE_F4 - 2 * TPB) r2 = src[threadIdx.x + 2 * TPB];
        }
        acc += row_core(l, yi, ly, stw);
        t = tn;
    }

    // remainder rows (B % TILE), handled by block 0 with direct global loads
    int rem = numTiles * TILE;
    if (blockIdx.x == 0) {
        int row = rem + threadIdx.x;
        if (row < B) {
            float l[KK];
#pragma unroll
            for (int k = 0; k < KK; k++) l[k] = logits[(size_t)row * KK + k];
            int yi = y[row];
            float ly = l[0];
#pragma unroll
            for (int k = 1; k < KK; k++) ly = (k == yi) ? l[k] : ly;
            acc += row_core(l, yi, ly, stw);
        }
    }

    // block reduction (deterministic order)
#pragma unroll
    for (int o = 16; o > 0; o >>= 1) acc += __shfl_xor_sync(0xffffffffu, acc, o);
    if ((threadIdx.x & 31) == 0) wsum[threadIdx.x >> 5] = acc;
    __syncthreads();
    if (threadIdx.x == 0) {
        float s = 0.f;
#pragma unroll
        for (int i = 0; i < TPB / 32; i++) s += wsum[i];
        g_part[blockIdx.x] = s;
        __threadfence();
        unsigned tk = atomicAdd(&g_ticket, 1u);
        s_last = (tk == GRID - 1);
    }
    __syncthreads();

    // last block folds all partials (fixed order -> deterministic)
    if (s_last) {
        float s = 0.f;
        for (int i = threadIdx.x; i < GRID; i += TPB) s += __ldcg(&g_part[i]);
#pragma unroll
        for (int o = 16; o > 0; o >>= 1) s += __shfl_xor_sync(0xffffffffu, s, o);
        if ((threadIdx.x & 31) == 0) wsum[threadIdx.x >> 5] = s;
        __syncthreads();
        if (threadIdx.x == 0) {
            float tt = 0.f;
#pragma unroll
            for (int i = 0; i < TPB / 32; i++) tt += wsum[i];
            out[0] = tt * invB;
            g_ticket = 0;   // reset so graph replays are deterministic
        }
    }
}

extern "C" void kernel_launch(void* const* d_in, const int* in_sizes, int n_in,
                              void* d_out, int out_size) {
    const float* logits = (const float*)d_in[0];
    const int*   y      = (const int*)d_in[1];
    int B = in_sizes[1];
    loss_kernel<<<GRID, TPB>>>(logits, y, (float*)d_out, B, 1.f / (float)B);
}